// round 7
// baseline (speedup 1.0000x reference)
#include <cuda_runtime.h>
#include <cuda_bf16.h>
#include <math.h>
#include <stdint.h>

#define BATCH 2
#define SEQ   2048
#define DMODEL 1024
#define NHEAD 16
#define DK    64
#define SCALE 0.35355339059327376f
#define M_TOT (BATCH * SEQ)

__device__ float g_q[BATCH * NHEAD * SEQ * DK];   // [bh][l][dk'] paired cols, tf32 rna
__device__ float g_k[BATCH * NHEAD * SEQ * DK];   // [bh][l][dk'] paired cols, tf32 rna
__device__ float g_v[BATCH * NHEAD * SEQ * DK];   // [bh][tile][kp][dk][2] key-paired, rna
__device__ float g_attn[BATCH * SEQ * DMODEL];    // [B,L,D]

__device__ __forceinline__ uint32_t f2tf(float f) {
    uint32_t u; asm("cvt.rna.tf32.f32 %0, %1;" : "=r"(u) : "f"(f)); return u;
}
__device__ __forceinline__ uint32_t smem_u32(const void* p) {
    uint32_t a;
    asm("{ .reg .u64 t; cvta.to.shared.u64 t, %1; cvt.u32.u64 %0, t; }" : "=r"(a) : "l"(p));
    return a;
}
__device__ __forceinline__ void mma_hw(float* c, const uint32_t* a, const uint32_t* b) {
    asm volatile(
        "mma.sync.aligned.m16n8k8.row.col.f32.tf32.tf32.f32 "
        "{%0,%1,%2,%3}, {%4,%5,%6,%7}, {%8,%9}, {%0,%1,%2,%3};\n"
        : "+f"(c[0]), "+f"(c[1]), "+f"(c[2]), "+f"(c[3])
        : "r"(a[0]), "r"(a[1]), "r"(a[2]), "r"(a[3]), "r"(b[0]), "r"(b[1]));
}

#define CP16(dst, src) asm volatile("cp.async.cg.shared.global [%0], [%1], 16;" :: "r"(dst), "l"(src) : "memory")
#define CP_COMMIT()    asm volatile("cp.async.commit_group;" ::: "memory")
#define CP_WAIT2()     asm volatile("cp.async.wait_group 2;" ::: "memory")
#define CP_WAIT1()     asm volatile("cp.async.wait_group 1;" ::: "memory")
#define CP_WAIT0()     asm volatile("cp.async.wait_group 0;" ::: "memory")

__device__ __forceinline__ int colperm(int dk) {
    return (dk & ~7) + ((dk & 3) << 1) + ((dk >> 2) & 1);
}

// ---------------- projection GEMM body (shared by QKV + O kernels) ---------
#define PPAD 36
__device__ __forceinline__ void proj_body(
    uint32_t* As, uint32_t* Bs,
    const float* __restrict__ X, const float* __restrict__ W,
    float* __restrict__ out, int mode, float scale, int bx, int by)
{
    const int tid = threadIdx.x, lane = tid & 31, warp = tid >> 5;
    const int wm = warp >> 1, wn = warp & 1, gr = lane >> 2, gc = lane & 3;
    const int m0 = by * 128, n0 = bx * 128;
    float acc[2][8][4] = {};

    float4 xa[4], wb[4];
#pragma unroll
    for (int p = 0; p < 4; p++) {
        int idx = tid + 256 * p;
        int r = idx >> 3, c = (idx & 7) * 4;
        xa[p] = *(const float4*)&X[(size_t)(m0 + r) * DMODEL + c];
        wb[p] = *(const float4*)&W[(size_t)(n0 + r) * DMODEL + c];
    }

    for (int k0 = 0; k0 < DMODEL; k0 += 32) {
#pragma unroll
        for (int p = 0; p < 4; p++) {
            int idx = tid + 256 * p;
            int r = idx >> 3, c = (idx & 7) * 4;
            uint32_t* pa = &As[r * PPAD + c];
            pa[0] = f2tf(xa[p].x); pa[1] = f2tf(xa[p].y); pa[2] = f2tf(xa[p].z); pa[3] = f2tf(xa[p].w);
            uint32_t* pb = &Bs[r * PPAD + c];
            pb[0] = f2tf(wb[p].x); pb[1] = f2tf(wb[p].y); pb[2] = f2tf(wb[p].z); pb[3] = f2tf(wb[p].w);
        }
        __syncthreads();
        if (k0 + 32 < DMODEL) {
#pragma unroll
            for (int p = 0; p < 4; p++) {
                int idx = tid + 256 * p;
                int r = idx >> 3, c = (idx & 7) * 4;
                xa[p] = *(const float4*)&X[(size_t)(m0 + r) * DMODEL + k0 + 32 + c];
                wb[p] = *(const float4*)&W[(size_t)(n0 + r) * DMODEL + k0 + 32 + c];
            }
        }
#pragma unroll
        for (int kk = 0; kk < 32; kk += 8) {
            uint32_t afr[2][4], bfr[8][2];
#pragma unroll
            for (int mt = 0; mt < 2; mt++) {
                int rm = wm * 32 + mt * 16;
                afr[mt][0] = As[(rm + gr) * PPAD + kk + gc];
                afr[mt][1] = As[(rm + 8 + gr) * PPAD + kk + gc];
                afr[mt][2] = As[(rm + gr) * PPAD + kk + 4 + gc];
                afr[mt][3] = As[(rm + 8 + gr) * PPAD + kk + 4 + gc];
            }
#pragma unroll
            for (int nt = 0; nt < 8; nt++) {
                int cn = wn * 64 + nt * 8;
                bfr[nt][0] = Bs[(cn + gr) * PPAD + kk + gc];
                bfr[nt][1] = Bs[(cn + gr) * PPAD + kk + 4 + gc];
            }
#pragma unroll
            for (int mt = 0; mt < 2; mt++)
#pragma unroll
                for (int nt = 0; nt < 8; nt++)
                    mma_hw(acc[mt][nt], afr[mt], bfr[nt]);
        }
        __syncthreads();
    }
#pragma unroll
    for (int mt = 0; mt < 2; mt++)
#pragma unroll
        for (int nt = 0; nt < 8; nt++)
#pragma unroll
            for (int half = 0; half < 2; half++) {
                int m = m0 + wm * 32 + mt * 16 + gr + half * 8;
                int n = n0 + wn * 64 + nt * 8 + gc * 2;
                float v0 = acc[mt][nt][half * 2 + 0] * scale;
                float v1 = acc[mt][nt][half * 2 + 1] * scale;
                if (mode == 0) {
                    *(float2*)(out + (size_t)m * DMODEL + n) = make_float2(v0, v1);
                } else {
                    int b = m >> 11, l = m & 2047, hh = n >> 6, dk = n & 63;
                    size_t base = ((size_t)b * NHEAD + hh) * SEQ * DK;
                    if (mode == 1) {
                        float* dst = out + base + (size_t)l * DK;
                        dst[colperm(dk)]     = __uint_as_float(f2tf(v0));
                        dst[colperm(dk + 1)] = __uint_as_float(f2tf(v1));
                    } else {
                        int tile = l >> 6, t = l & 63;
                        int kp = ((t >> 3) << 2) + (t & 3), hp = (t >> 2) & 1;
                        float* dst = out + base + (size_t)tile * 4096 + ((kp << 6) + dk) * 2 + hp;
                        dst[0] = __uint_as_float(f2tf(v0));
                        dst[2] = __uint_as_float(f2tf(v1));
                    }
                }
            }
}

__global__ __launch_bounds__(256) void proj_qkv(
    const float* __restrict__ Xq, const float* __restrict__ Xk, const float* __restrict__ Xv,
    const float* __restrict__ Wq, const float* __restrict__ Wk, const float* __restrict__ Wv,
    float* __restrict__ oq, float* __restrict__ ok, float* __restrict__ ov)
{
    __shared__ uint32_t As[128 * PPAD];
    __shared__ uint32_t Bs[128 * PPAD];
    const int z = blockIdx.z;
    const float* X = (z == 0) ? Xq : (z == 1) ? Xk : Xv;
    const float* W = (z == 0) ? Wq : (z == 1) ? Wk : Wv;
    float* out     = (z == 0) ? oq : (z == 1) ? ok : ov;
    proj_body(As, Bs, X, W, out, (z == 2) ? 2 : 1, (z == 2) ? 1.0f : SCALE,
              blockIdx.x, blockIdx.y);
}

__global__ __launch_bounds__(256) void proj_o(
    const float* __restrict__ X, const float* __restrict__ W, float* __restrict__ out)
{
    __shared__ uint32_t As[128 * PPAD];
    __shared__ uint32_t Bs[128 * PPAD];
    proj_body(As, Bs, X, W, out, 0, 1.0f, blockIdx.x, blockIdx.y);
}

// ---------------- flash attention: swizzled smem, 4 CTAs/SM ----------------
// K: two buffers 64x64 floats, XOR swizzle on 8B units: u8' = u8 ^ ((row&7)<<2)
// V: one buffer 32x128 floats (key-paired), u8' = u8 ^ ((kp&7)<<3)
#define KB0 0
#define KB1 4096
#define VBF 8192
#define SMEM_ATT (12288 * 4)   // 49152 bytes

__global__ __launch_bounds__(128, 4) void attn_cp(
    const float* __restrict__ q, const float* __restrict__ k,
    const float* __restrict__ v, const float* __restrict__ pb,
    float* __restrict__ out)
{
    extern __shared__ float smf[];
    const uint32_t sb = smem_u32(smf);
    const int tid = threadIdx.x, lane = tid & 31, warp = tid >> 5;
    const int gr = lane >> 2, gc = lane & 3;
    const int bh = blockIdx.y, qb = blockIdx.x * 64;
    const int T = SEQ / 64;

    // Q fragments: paired-col gmem, pre-rounded
    uint32_t qa[8][4];
    {
        const float* qg = q + ((size_t)bh * SEQ + qb + warp * 16) * DK;
#pragma unroll
        for (int ks = 0; ks < 8; ks++) {
            uint2 t0 = *(const uint2*)&qg[(size_t)gr * DK + ks * 8 + gc * 2];
            uint2 t1 = *(const uint2*)&qg[(size_t)(gr + 8) * DK + ks * 8 + gc * 2];
            qa[ks][0] = t0.x; qa[ks][2] = t0.y;
            qa[ks][1] = t1.x; qa[ks][3] = t1.y;
        }
    }

    float mrow[2] = {-INFINITY, -INFINITY};
    float lrow[2] = {0.f, 0.f};
    float oacc[8][4] = {};

    const float* kbase = k + (size_t)bh * SEQ * DK;
    const float* vbase = v + (size_t)bh * SEQ * DK;
    const float* pbbase = pb + ((size_t)bh * SEQ + qb + warp * 16) * SEQ;

    // prologue: K(0) group, V(0) group
    {
        const float4* kg = (const float4*)kbase;
#pragma unroll
        for (int j = 0; j < 8; j++) {
            int c = tid + 128 * j;
            int r = c >> 4, c16 = c & 15;
            CP16(sb + (KB0 + r * 64) * 4 + (c16 ^ ((r & 7) << 1)) * 16, kg + c);
        }
        CP_COMMIT();
        const float4* vg = (const float4*)vbase;
#pragma unroll
        for (int j = 0; j < 8; j++) {
            int c = tid + 128 * j;
            int kp = c >> 5, c16 = c & 31;
            CP16(sb + (VBF + kp * 128) * 4 + (c16 ^ ((kp & 7) << 2)) * 16, vg + c);
        }
        CP_COMMIT();
    }

    for (int kt = 0; kt < T; kt++) {
        const int cur = kt & 1;
        const int kb = kt * 64;

        // issue K(t+1) into alternate buffer
        if (kt + 1 < T) {
            const float4* kg = (const float4*)(kbase + (size_t)(kb + 64) * DK);
            const int kf = cur ? KB0 : KB1;
#pragma unroll
            for (int j = 0; j < 8; j++) {
                int c = tid + 128 * j;
                int r = c >> 4, c16 = c & 15;
                CP16(sb + (kf + r * 64) * 4 + (c16 ^ ((r & 7) << 1)) * 16, kg + c);
            }
            CP_COMMIT();
        }

        // posbias -> S accumulator init (MMA accumulates QK^T on top)
        float sacc[8][4];
#pragma unroll
        for (int nt = 0; nt < 8; nt++) {
            float2 p0 = *(const float2*)&pbbase[(size_t)gr * SEQ + kb + nt * 8 + gc * 2];
            float2 p1 = *(const float2*)&pbbase[(size_t)(gr + 8) * SEQ + kb + nt * 8 + gc * 2];
            sacc[nt][0] = p0.x; sacc[nt][1] = p0.y;
            sacc[nt][2] = p1.x; sacc[nt][3] = p1.y;
        }

        if (kt + 1 < T) { CP_WAIT2(); } else { CP_WAIT1(); }
        __syncthreads();

        const float* Kc = smf + (cur ? KB1 : KB0);
        const float* Vc = smf + VBF;

        // S += Q K^T  (nt-outer: bias LDG slack grows with nt)
#pragma unroll
        for (int nt = 0; nt < 8; nt++) {
            const int row = nt * 8 + gr;
            const int sw = (row & 7) << 2;
#pragma unroll
            for (int ks = 0; ks < 8; ks++) {
                uint2 b = *(const uint2*)&Kc[row * 64 + ((ks * 4 + gc) ^ sw) * 2];
                uint32_t bfr[2] = { b.x, b.y };
                mma_hw(sacc[nt], qa[ks], bfr);
            }
        }

        if (kt + 1 < T) { CP_WAIT1(); } else { CP_WAIT0(); }
        __syncthreads();   // all warps: S-MMA done (K buf -> P), V(t) visible

        // online softmax
#pragma unroll
        for (int r = 0; r < 2; r++) {
            float mx = -INFINITY;
#pragma unroll
            for (int nt = 0; nt < 8; nt++)
                mx = fmaxf(mx, fmaxf(sacc[nt][r * 2], sacc[nt][r * 2 + 1]));
            mx = fmaxf(mx, __shfl_xor_sync(0xffffffffu, mx, 1));
            mx = fmaxf(mx, __shfl_xor_sync(0xffffffffu, mx, 2));
            float mn = fmaxf(mrow[r], mx);
            float al = __expf(mrow[r] - mn);
            float rs = 0.f;
#pragma unroll
            for (int nt = 0; nt < 8; nt++) {
                sacc[nt][r * 2]     = __expf(sacc[nt][r * 2] - mn);
                sacc[nt][r * 2 + 1] = __expf(sacc[nt][r * 2 + 1] - mn);
                rs += sacc[nt][r * 2] + sacc[nt][r * 2 + 1];
            }
            rs += __shfl_xor_sync(0xffffffffu, rs, 1);
            rs += __shfl_xor_sync(0xffffffffu, rs, 2);
            lrow[r] = lrow[r] * al + rs;
            mrow[r] = mn;
#pragma unroll
            for (int dt = 0; dt < 8; dt++) {
                oacc[dt][r * 2]     *= al;
                oacc[dt][r * 2 + 1] *= al;
            }
        }

        // P (rna tf32) into K buffer, swizzled, own warp rows
        {
            float* Pc = (float*)Kc;
            const int rm = warp * 16;
#pragma unroll
            for (int nt = 0; nt < 8; nt++) {
                int r0 = rm + gr, r1 = rm + 8 + gr;
                *(uint2*)&Pc[r0 * 64 + ((nt * 4 + gc) ^ ((r0 & 7) << 2)) * 2] =
                    make_uint2(f2tf(sacc[nt][0]), f2tf(sacc[nt][1]));
                *(uint2*)&Pc[r1 * 64 + ((nt * 4 + gc) ^ ((r1 & 7) << 2)) * 2] =
                    make_uint2(f2tf(sacc[nt][2]), f2tf(sacc[nt][3]));
            }
        }
        __syncwarp();

        // O += P @ V
        {
            const float* Pc = Kc;
            const int rm = warp * 16;
#pragma unroll
            for (int ks = 0; ks < 8; ks++) {
                uint32_t pa[4];
                int r0 = rm + gr, r1 = rm + 8 + gr;
                int u0 = ((ks * 4 + (gc >> 1)) ^ ((r0 & 7) << 2)) * 2 + (gc & 1);
                int u1 = ((ks * 4 + 2 + (gc >> 1)) ^ ((r0 & 7) << 2)) * 2 + (gc & 1);
                pa[0] = __float_as_uint(Pc[r0 * 64 + u0]);
                pa[1] = __float_as_uint(Pc[r1 * 64 + u0]);
                pa[2] = __float_as_uint(Pc[r0 * 64 + u1]);
                pa[3] = __float_as_uint(Pc[r1 * 64 + u1]);
                const int kp = ks * 4 + gc;
                const int swv = (kp & 7) << 3;
#pragma unroll
                for (int dt = 0; dt < 8; dt++) {
                    uint2 b = *(const uint2*)&Vc[kp * 128 + ((dt * 8 + gr) ^ swv) * 2];
                    uint32_t bfr[2] = { b.x, b.y };
                    mma_hw(oacc[dt], pa, bfr);
                }
            }
        }
        __syncthreads();   // all PV reads of V(t) done before V(t+1) streams in

        if (kt + 1 < T) {
            const float4* vg = (const float4*)(vbase + (size_t)(kt + 1) * 4096);
#pragma unroll
            for (int j = 0; j < 8; j++) {
                int c = tid + 128 * j;
                int kp = c >> 5, c16 = c & 31;
                CP16(sb + (VBF + kp * 128) * 4 + (c16 ^ ((kp & 7) << 2)) * 16, vg + c);
            }
            CP_COMMIT();
        }
    }

    const int b = bh >> 4, h = bh & 15;
    float inv0 = 1.f / lrow[0];
    float inv1 = 1.f / lrow[1];
    float* dst = out + ((size_t)b * SEQ + qb + warp * 16) * DMODEL + h * DK;
#pragma unroll
    for (int dt = 0; dt < 8; dt++) {
        *(float2*)&dst[(size_t)gr * DMODEL + dt * 8 + gc * 2] =
            make_float2(oacc[dt][0] * inv0, oacc[dt][1] * inv0);
        *(float2*)&dst[(size_t)(gr + 8) * DMODEL + dt * 8 + gc * 2] =
            make_float2(oacc[dt][2] * inv1, oacc[dt][3] * inv1);
    }
}

// ---------------- launch ----------------------------------------------------
extern "C" void kernel_launch(void* const* d_in, const int* in_sizes, int n_in,
                              void* d_out, int out_size)
{
    const float* query = (const float*)d_in[0];
    const float* key   = (const float*)d_in[1];
    const float* value = (const float*)d_in[2];
    const float* pbias = (const float*)d_in[3];
    const float* Wq    = (const float*)d_in[4];
    const float* Wk    = (const float*)d_in[5];
    const float* Wv    = (const float*)d_in[6];
    const float* Wo    = (const float*)d_in[7];
    float* out = (float*)d_out;

    float *qp, *kp, *vp, *ap;
    cudaGetSymbolAddress((void**)&qp, g_q);
    cudaGetSymbolAddress((void**)&kp, g_k);
    cudaGetSymbolAddress((void**)&vp, g_v);
    cudaGetSymbolAddress((void**)&ap, g_attn);

    cudaFuncSetAttribute(attn_cp, cudaFuncAttributeMaxDynamicSharedMemorySize, SMEM_ATT);

    dim3 qkvgrid(DMODEL / 128, M_TOT / 128, 3);   // (8, 32, 3) = 768 CTAs
    proj_qkv<<<qkvgrid, 256>>>(query, key, value, Wq, Wk, Wv, qp, kp, vp);

    dim3 agrid(SEQ / 64, BATCH * NHEAD);          // (32, 32)
    attn_cp<<<agrid, 128, SMEM_ATT>>>(qp, kp, vp, pbias, ap);

    dim3 ogrid(DMODEL / 128, M_TOT / 128);        // (8, 32)
    proj_o<<<ogrid, 256>>>(ap, Wo, out);
}

// round 10
// speedup vs baseline: 1.1257x; 1.1257x over previous
#include <cuda_runtime.h>
#include <cuda_bf16.h>
#include <math.h>
#include <stdint.h>

#define BATCH 2
#define SEQ   2048
#define DMODEL 1024
#define NHEAD 16
#define DK    64
#define SCALE 0.35355339059327376f
#define M_TOT (BATCH * SEQ)

__device__ float g_q[BATCH * NHEAD * SEQ * DK];   // [bh][l][dk'] paired cols, tf32 rna
__device__ float g_k[BATCH * NHEAD * SEQ * DK];   // [bh][l][dk'] paired cols, tf32 rna
__device__ float g_v[BATCH * NHEAD * SEQ * DK];   // [bh][tile][kp][dk][2] key-paired, rna
__device__ float g_attn[BATCH * SEQ * DMODEL];    // [B,L,D]

__device__ __forceinline__ uint32_t f2tf(float f) {
    uint32_t u; asm("cvt.rna.tf32.f32 %0, %1;" : "=r"(u) : "f"(f)); return u;
}
__device__ __forceinline__ uint32_t smem_u32(const void* p) {
    uint32_t a;
    asm("{ .reg .u64 t; cvta.to.shared.u64 t, %1; cvt.u32.u64 %0, t; }" : "=r"(a) : "l"(p));
    return a;
}
__device__ __forceinline__ void mma_hw(float* c, const uint32_t* a, const uint32_t* b) {
    asm volatile(
        "mma.sync.aligned.m16n8k8.row.col.f32.tf32.tf32.f32 "
        "{%0,%1,%2,%3}, {%4,%5,%6,%7}, {%8,%9}, {%0,%1,%2,%3};\n"
        : "+f"(c[0]), "+f"(c[1]), "+f"(c[2]), "+f"(c[3])
        : "r"(a[0]), "r"(a[1]), "r"(a[2]), "r"(a[3]), "r"(b[0]), "r"(b[1]));
}

#define CP16(dst, src) asm volatile("cp.async.cg.shared.global [%0], [%1], 16;" :: "r"(dst), "l"(src) : "memory")
#define CP_COMMIT()    asm volatile("cp.async.commit_group;" ::: "memory")
#define CP_WAIT2()     asm volatile("cp.async.wait_group 2;" ::: "memory")
#define CP_WAIT1()     asm volatile("cp.async.wait_group 1;" ::: "memory")
#define CP_WAIT0()     asm volatile("cp.async.wait_group 0;" ::: "memory")

__device__ __forceinline__ int colperm(int dk) {
    return (dk & ~7) + ((dk & 3) << 1) + ((dk >> 2) & 1);
}

// ---------------- projection GEMM: cp.async double-buffered ----------------
// Raw fp32 staged in smem; rna f2tf applied at fragment load (precision
// identical to store-side cvt). 2 CTAs/SM.
#define PPAD 36
#define PBUF (128 * PPAD)                 // floats per buffer per matrix
#define PROJ_SMEM (4 * PBUF * 4)          // 73728 bytes (A0,B0,A1,B1)

__device__ __forceinline__ void proj_body(
    float* Asr, float* Bsr, uint32_t sbA, uint32_t sbB,
    const float* __restrict__ X, const float* __restrict__ W,
    float* __restrict__ out, int mode, float scale, int bx, int by)
{
    const int tid = threadIdx.x, lane = tid & 31, warp = tid >> 5;
    const int wm = warp >> 1, wn = warp & 1, gr = lane >> 2, gc = lane & 3;
    const int m0 = by * 128, n0 = bx * 128;
    float acc[2][8][4] = {};

    // prologue: stage 0
#pragma unroll
    for (int j = 0; j < 4; j++) {
        int c = tid + 256 * j;
        int r = c >> 3, c4 = (c & 7) * 4;
        CP16(sbA + (r * PPAD + c4) * 4, &X[(size_t)(m0 + r) * DMODEL + c4]);
        CP16(sbB + (r * PPAD + c4) * 4, &W[(size_t)(n0 + r) * DMODEL + c4]);
    }
    CP_COMMIT();

    for (int it = 0; it < 32; it++) {
        const int buf = it & 1;
        if (it + 1 < 32) {
            const int nb = (it + 1) & 1;
            const int k0 = (it + 1) * 32;
#pragma unroll
            for (int j = 0; j < 4; j++) {
                int c = tid + 256 * j;
                int r = c >> 3, c4 = (c & 7) * 4;
                CP16(sbA + (nb * 2 * PBUF + r * PPAD + c4) * 4,
                     &X[(size_t)(m0 + r) * DMODEL + k0 + c4]);
                CP16(sbB + (nb * 2 * PBUF + r * PPAD + c4) * 4,
                     &W[(size_t)(n0 + r) * DMODEL + k0 + c4]);
            }
            CP_COMMIT();
            CP_WAIT1();
        } else {
            CP_WAIT0();
        }
        __syncthreads();

        const float* As = Asr + buf * 2 * PBUF;
        const float* Bs = Bsr + buf * 2 * PBUF;
#pragma unroll
        for (int kk = 0; kk < 32; kk += 8) {
            uint32_t afr[2][4], bfr[8][2];
#pragma unroll
            for (int mt = 0; mt < 2; mt++) {
                int rm = wm * 32 + mt * 16;
                afr[mt][0] = f2tf(As[(rm + gr) * PPAD + kk + gc]);
                afr[mt][1] = f2tf(As[(rm + 8 + gr) * PPAD + kk + gc]);
                afr[mt][2] = f2tf(As[(rm + gr) * PPAD + kk + 4 + gc]);
                afr[mt][3] = f2tf(As[(rm + 8 + gr) * PPAD + kk + 4 + gc]);
            }
#pragma unroll
            for (int nt = 0; nt < 8; nt++) {
                int cn = wn * 64 + nt * 8;
                bfr[nt][0] = f2tf(Bs[(cn + gr) * PPAD + kk + gc]);
                bfr[nt][1] = f2tf(Bs[(cn + gr) * PPAD + kk + 4 + gc]);
            }
#pragma unroll
            for (int mt = 0; mt < 2; mt++)
#pragma unroll
                for (int nt = 0; nt < 8; nt++)
                    mma_hw(acc[mt][nt], afr[mt], bfr[nt]);
        }
        __syncthreads();
    }

#pragma unroll
    for (int mt = 0; mt < 2; mt++)
#pragma unroll
        for (int nt = 0; nt < 8; nt++)
#pragma unroll
            for (int half = 0; half < 2; half++) {
                int m = m0 + wm * 32 + mt * 16 + gr + half * 8;
                int n = n0 + wn * 64 + nt * 8 + gc * 2;
                float v0 = acc[mt][nt][half * 2 + 0] * scale;
                float v1 = acc[mt][nt][half * 2 + 1] * scale;
                if (mode == 0) {
                    *(float2*)(out + (size_t)m * DMODEL + n) = make_float2(v0, v1);
                } else {
                    int b = m >> 11, l = m & 2047, hh = n >> 6, dk = n & 63;
                    size_t base = ((size_t)b * NHEAD + hh) * SEQ * DK;
                    if (mode == 1) {
                        float* dst = out + base + (size_t)l * DK;
                        dst[colperm(dk)]     = __uint_as_float(f2tf(v0));
                        dst[colperm(dk + 1)] = __uint_as_float(f2tf(v1));
                    } else {
                        int tile = l >> 6, t = l & 63;
                        int kp = ((t >> 3) << 2) + (t & 3), hp = (t >> 2) & 1;
                        float* dst = out + base + (size_t)tile * 4096 + ((kp << 6) + dk) * 2 + hp;
                        dst[0] = __uint_as_float(f2tf(v0));
                        dst[2] = __uint_as_float(f2tf(v1));
                    }
                }
            }
}

__global__ __launch_bounds__(256, 2) void proj_qkv(
    const float* __restrict__ Xq, const float* __restrict__ Xk, const float* __restrict__ Xv,
    const float* __restrict__ Wq, const float* __restrict__ Wk, const float* __restrict__ Wv,
    float* __restrict__ oq, float* __restrict__ ok, float* __restrict__ ov)
{
    extern __shared__ float psm[];
    float* Asr = psm;                 // [buf][128*PPAD] interleaved as A0,B0,A1,B1
    float* Bsr = psm + PBUF;
    uint32_t sbA = smem_u32(Asr), sbB = smem_u32(Bsr);
    const int z = blockIdx.z;
    const float* X = (z == 0) ? Xq : (z == 1) ? Xk : Xv;
    const float* W = (z == 0) ? Wq : (z == 1) ? Wk : Wv;
    float* out     = (z == 0) ? oq : (z == 1) ? ok : ov;
    proj_body(Asr, Bsr, sbA, sbB, X, W, out, (z == 2) ? 2 : 1,
              (z == 2) ? 1.0f : SCALE, blockIdx.x, blockIdx.y);
}

__global__ __launch_bounds__(256, 2) void proj_o(
    const float* __restrict__ X, const float* __restrict__ W, float* __restrict__ out)
{
    extern __shared__ float psm[];
    float* Asr = psm;
    float* Bsr = psm + PBUF;
    proj_body(Asr, Bsr, smem_u32(Asr), smem_u32(Bsr), X, W, out, 0, 1.0f,
              blockIdx.x, blockIdx.y);
}

// ---------------- flash attention (R6 version, 316us — reverted) -----------
#define KSTR 72
#define PSTR 68
#define VSTR 136
#define K0F  0
#define K1F  (64 * KSTR)
#define V0F  (2 * 64 * KSTR)
#define V1F  (2 * 64 * KSTR + 32 * VSTR)
#define SMEM_ATT ((2 * 64 * KSTR + 2 * 32 * VSTR) * 4)   // 71680 bytes

__global__ __launch_bounds__(128, 3) void attn_cp(
    const float* __restrict__ q, const float* __restrict__ k,
    const float* __restrict__ v, const float* __restrict__ pb,
    float* __restrict__ out)
{
    extern __shared__ float smf[];
    const uint32_t sb = smem_u32(smf);
    const int tid = threadIdx.x, lane = tid & 31, warp = tid >> 5;
    const int gr = lane >> 2, gc = lane & 3;
    const int bh = blockIdx.y, qb = blockIdx.x * 64;

    uint32_t qa[8][4];
    {
        const float* qg = q + ((size_t)bh * SEQ + qb + warp * 16) * DK;
#pragma unroll
        for (int ks = 0; ks < 8; ks++) {
            uint2 t0 = *(const uint2*)&qg[(size_t)gr * DK + ks * 8 + gc * 2];
            uint2 t1 = *(const uint2*)&qg[(size_t)(gr + 8) * DK + ks * 8 + gc * 2];
            qa[ks][0] = t0.x; qa[ks][2] = t0.y;
            qa[ks][1] = t1.x; qa[ks][3] = t1.y;
        }
    }

    float mrow[2] = {-INFINITY, -INFINITY};
    float lrow[2] = {0.f, 0.f};
    float oacc[8][4] = {};

    const float* kbase = k + (size_t)bh * SEQ * DK;
    const float* vbase = v + (size_t)bh * SEQ * DK;
    const float* pbbase = pb + ((size_t)bh * SEQ + qb + warp * 16) * SEQ;

    {
        const float4* kg = (const float4*)kbase;
        const float4* vg = (const float4*)vbase;
#pragma unroll
        for (int j = 0; j < 8; j++) {
            int c = tid + 128 * j;
            CP16(sb + (K0F + (c >> 4) * KSTR + (c & 15) * 4) * 4, kg + c);
            CP16(sb + (V0F + (c >> 5) * VSTR + (c & 31) * 4) * 4, vg + c);
        }
        CP_COMMIT();
    }

    for (int kt = 0; kt < SEQ / 64; kt++) {
        const int cur = kt & 1;
        const int kb = kt * 64;

        if (kt + 1 < SEQ / 64) {
            const float4* kg = (const float4*)(kbase + (size_t)(kb + 64) * DK);
            const float4* vg = (const float4*)(vbase + (size_t)(kt + 1) * 4096);
            const int kf = cur ? K0F : K1F;
            const int vf = cur ? V0F : V1F;
#pragma unroll
            for (int j = 0; j < 8; j++) {
                int c = tid + 128 * j;
                CP16(sb + (kf + (c >> 4) * KSTR + (c & 15) * 4) * 4, kg + c);
                CP16(sb + (vf + (c >> 5) * VSTR + (c & 31) * 4) * 4, vg + c);
            }
            CP_COMMIT();
        }

        float2 pbv[16];
#pragma unroll
        for (int nt = 0; nt < 8; nt++) {
            pbv[nt]     = *(const float2*)&pbbase[(size_t)gr * SEQ + kb + nt * 8 + gc * 2];
            pbv[8 + nt] = *(const float2*)&pbbase[(size_t)(gr + 8) * SEQ + kb + nt * 8 + gc * 2];
        }

        if (kt + 1 < SEQ / 64) { CP_WAIT1(); } else { CP_WAIT0(); }
        __syncthreads();

        const float* Kc = smf + (cur ? K1F : K0F);
        const float* Vc = smf + (cur ? V1F : V0F);

        float sacc[8][4] = {};
#pragma unroll
        for (int ks = 0; ks < 8; ks++) {
#pragma unroll
            for (int nt = 0; nt < 8; nt++) {
                uint2 b = *(const uint2*)&Kc[(nt * 8 + gr) * KSTR + ks * 8 + gc * 2];
                uint32_t bfr[2] = { b.x, b.y };
                mma_hw(sacc[nt], qa[ks], bfr);
            }
        }
        __syncthreads();

#pragma unroll
        for (int nt = 0; nt < 8; nt++) {
            sacc[nt][0] += pbv[nt].x;     sacc[nt][1] += pbv[nt].y;
            sacc[nt][2] += pbv[8 + nt].x; sacc[nt][3] += pbv[8 + nt].y;
        }

#pragma unroll
        for (int r = 0; r < 2; r++) {
            float mx = -INFINITY;
#pragma unroll
            for (int nt = 0; nt < 8; nt++)
                mx = fmaxf(mx, fmaxf(sacc[nt][r * 2], sacc[nt][r * 2 + 1]));
            mx = fmaxf(mx, __shfl_xor_sync(0xffffffffu, mx, 1));
            mx = fmaxf(mx, __shfl_xor_sync(0xffffffffu, mx, 2));
            float mn = fmaxf(mrow[r], mx);
            float al = __expf(mrow[r] - mn);
            float rs = 0.f;
#pragma unroll
            for (int nt = 0; nt < 8; nt++) {
                sacc[nt][r * 2]     = __expf(sacc[nt][r * 2] - mn);
                sacc[nt][r * 2 + 1] = __expf(sacc[nt][r * 2 + 1] - mn);
                rs += sacc[nt][r * 2] + sacc[nt][r * 2 + 1];
            }
            rs += __shfl_xor_sync(0xffffffffu, rs, 1);
            rs += __shfl_xor_sync(0xffffffffu, rs, 2);
            lrow[r] = lrow[r] * al + rs;
            mrow[r] = mn;
#pragma unroll
            for (int dt = 0; dt < 8; dt++) {
                oacc[dt][r * 2]     *= al;
                oacc[dt][r * 2 + 1] *= al;
            }
        }

        {
            float* Pc = (float*)Kc;
            int rm = warp * 16;
#pragma unroll
            for (int nt = 0; nt < 8; nt++) {
                *(uint2*)&Pc[(rm + gr) * PSTR + nt * 8 + gc * 2] =
                    make_uint2(f2tf(sacc[nt][0]), f2tf(sacc[nt][1]));
                *(uint2*)&Pc[(rm + 8 + gr) * PSTR + nt * 8 + gc * 2] =
                    make_uint2(f2tf(sacc[nt][2]), f2tf(sacc[nt][3]));
            }
        }
        __syncwarp();

        {
            const float* Pc = Kc;
            int rm = warp * 16;
#pragma unroll
            for (int ks = 0; ks < 8; ks++) {
                uint32_t pa[4];
                pa[0] = __float_as_uint(Pc[(rm + gr) * PSTR + ks * 8 + gc]);
                pa[1] = __float_as_uint(Pc[(rm + 8 + gr) * PSTR + ks * 8 + gc]);
                pa[2] = __float_as_uint(Pc[(rm + gr) * PSTR + ks * 8 + 4 + gc]);
                pa[3] = __float_as_uint(Pc[(rm + 8 + gr) * PSTR + ks * 8 + 4 + gc]);
#pragma unroll
                for (int dt = 0; dt < 8; dt++) {
                    uint2 b = *(const uint2*)&Vc[(ks * 4 + gc) * VSTR + (dt * 8 + gr) * 2];
                    uint32_t bfr[2] = { b.x, b.y };
                    mma_hw(oacc[dt], pa, bfr);
                }
            }
        }
        __syncthreads();
    }

    const int b = bh >> 4, h = bh & 15;
    float inv0 = 1.f / lrow[0];
    float inv1 = 1.f / lrow[1];
    float* dst = out + ((size_t)b * SEQ + qb + warp * 16) * DMODEL + h * DK;
#pragma unroll
    for (int dt = 0; dt < 8; dt++) {
        *(float2*)&dst[(size_t)gr * DMODEL + dt * 8 + gc * 2] =
            make_float2(oacc[dt][0] * inv0, oacc[dt][1] * inv0);
        *(float2*)&dst[(size_t)(gr + 8) * DMODEL + dt * 8 + gc * 2] =
            make_float2(oacc[dt][2] * inv1, oacc[dt][3] * inv1);
    }
}

// ---------------- launch ----------------------------------------------------
extern "C" void kernel_launch(void* const* d_in, const int* in_sizes, int n_in,
                              void* d_out, int out_size)
{
    const float* query = (const float*)d_in[0];
    const float* key   = (const float*)d_in[1];
    const float* value = (const float*)d_in[2];
    const float* pbias = (const float*)d_in[3];
    const float* Wq    = (const float*)d_in[4];
    const float* Wk    = (const float*)d_in[5];
    const float* Wv    = (const float*)d_in[6];
    const float* Wo    = (const float*)d_in[7];
    float* out = (float*)d_out;

    float *qp, *kp, *vp, *ap;
    cudaGetSymbolAddress((void**)&qp, g_q);
    cudaGetSymbolAddress((void**)&kp, g_k);
    cudaGetSymbolAddress((void**)&vp, g_v);
    cudaGetSymbolAddress((void**)&ap, g_attn);

    cudaFuncSetAttribute(attn_cp, cudaFuncAttributeMaxDynamicSharedMemorySize, SMEM_ATT);
    cudaFuncSetAttribute(proj_qkv, cudaFuncAttributeMaxDynamicSharedMemorySize, PROJ_SMEM);
    cudaFuncSetAttribute(proj_o,   cudaFuncAttributeMaxDynamicSharedMemorySize, PROJ_SMEM);

    dim3 qkvgrid(DMODEL / 128, M_TOT / 128, 3);   // (8, 32, 3)
    proj_qkv<<<qkvgrid, 256, PROJ_SMEM>>>(query, key, value, Wq, Wk, Wv, qp, kp, vp);

    dim3 agrid(SEQ / 64, BATCH * NHEAD);          // (32, 32)
    attn_cp<<<agrid, 128, SMEM_ATT>>>(qp, kp, vp, pbias, ap);

    dim3 ogrid(DMODEL / 128, M_TOT / 128);        // (8, 32)
    proj_o<<<ogrid, 256, PROJ_SMEM>>>(ap, Wo, out);
}